// round 16
// baseline (speedup 1.0000x reference)
#include <cuda_runtime.h>
#include <cuda_bf16.h>
#include <math.h>
#include <stdint.h>

#define NP   512
#define MNP  4096
#define BSZ  8
#define DIM  256
#define NH   8
#define TOPK 32
#define CAND 48
#define FF   2048
#define HD   32
#define LN_EPS 1e-5f
#define ATT_SCALE 0.17677669529663687f   /* 1/sqrt(32) */

// ---------------------------------------------------------------------------
// Scratch
// ---------------------------------------------------------------------------
__device__ uint32_t g_usim [BSZ * NP * MNP];
__device__ float g_mnorm [MNP * BSZ];
__device__ int   g_cand  [BSZ * NP * CAND];
__device__ int   g_rns   [BSZ * NP * TOPK];
__device__ float g_K     [MNP * BSZ * DIM];
__device__ float g_V     [MNP * BSZ * DIM];
__device__ float g_Q     [NP * BSZ * DIM];
__device__ float g_t1    [NP * BSZ * DIM];
__device__ float g_QK2   [NP * BSZ * 2 * DIM];
__device__ float g_V2    [NP * BSZ * DIM];
__device__ float g_sa    [NP * BSZ * DIM];
__device__ float g_sa2   [NP * BSZ * DIM];
__device__ float g_t2    [NP * BSZ * DIM];
__device__ float g_ffh   [NP * BSZ * FF];
__device__ float g_ffo   [4 * NP * BSZ * DIM];
__device__ float g_madd  [MNP * BSZ * DIM];
__device__ float g_qadd  [NP * BSZ * DIM];

__device__ __forceinline__ float ftf32(float x) {
    uint32_t u;
    asm("cvt.rna.tf32.f32 %0, %1;" : "=r"(u) : "f"(x));
    return __uint_as_float(u);
}
__device__ __forceinline__ void cpa16(uint32_t dst, const float* src) {
    asm volatile("cp.async.cg.shared.global [%0], [%1], 16;" :: "r"(dst), "l"(src));
}
__device__ __forceinline__ uint32_t ordermap(float v) {
    uint32_t u = __float_as_uint(v);
    return (u & 0x80000000u) ? ~u : (u | 0x80000000u);
}

// ---------------------------------------------------------------------------
// Fused pre: madd = memory+kpos, mnorm, qadd = tgt+qpos
// ---------------------------------------------------------------------------
__global__ void pre_kernel(const float* __restrict__ mem, const float* __restrict__ kp,
                           float* __restrict__ madd, float* __restrict__ mnorm,
                           const float* __restrict__ tg, const float* __restrict__ qp,
                           float* __restrict__ qadd)
{
    const int MBROWS = MNP * BSZ;
    int blk = blockIdx.x;
    int t = threadIdx.x;
    if (blk < MBROWS / 8) {
        int w = t >> 5, lane = t & 31;
        long r = (long)blk * 8 + w;
        const float* src = mem + r * DIM;
        const float* kpr = kp + r * DIM;
        float* dst = madd + r * DIM;
        float s = 0.f;
        #pragma unroll
        for (int i = 0; i < 2; i++) {
            int d = lane * 4 + i * 128;
            float4 v = *reinterpret_cast<const float4*>(src + d);
            s = fmaf(v.x, v.x, s); s = fmaf(v.y, v.y, s);
            s = fmaf(v.z, v.z, s); s = fmaf(v.w, v.w, s);
            float4 k = *reinterpret_cast<const float4*>(kpr + d);
            v.x += k.x; v.y += k.y; v.z += k.z; v.w += k.w;
            *reinterpret_cast<float4*>(dst + d) = v;
        }
        #pragma unroll
        for (int o = 16; o; o >>= 1) s += __shfl_xor_sync(0xffffffffu, s, o);
        if (lane == 0) mnorm[r] = 1.0f / sqrtf(s);
    } else {
        int i = (blk - MBROWS / 8) * 1024 + t;
        #pragma unroll
        for (int j = 0; j < 4; j++) {
            int e = i + j * 256;
            float4 x = ((const float4*)tg)[e];
            float4 y = ((const float4*)qp)[e];
            x.x += y.x; x.y += y.y; x.z += y.z; x.w += y.w;
            ((float4*)qadd)[e] = x;
        }
    }
}

// ---------------------------------------------------------------------------
// TF32 NT GEMM, BN=64, 256 threads, 3 CTA/SM (unchanged proven path).
// ACT: 0 none, 1 GELU.
// ---------------------------------------------------------------------------
template<int ACT>
__global__ void __launch_bounds__(256, 3) tgemm_nt64(
    const float* __restrict__ A, const float* __restrict__ B,
    const float* __restrict__ bias, float* __restrict__ C,
    int R, int Cc, int K, int lda, int ldb, int ldc,
    long sA1, long sA2, long sB1, long sB2, long sC1, long sC2, long sBias2,
    int Z2, float alpha)
{
    constexpr int BM = 128, BN = 64, BK = 16, P = 20;
    constexpr int STAGE = (BM + BN) * P;
    __shared__ float sm[3 * STAGE];

    const int z  = blockIdx.z;
    const int z1 = z / Z2, z2 = z % Z2;
    A += z1 * sA1 + z2 * sA2;
    B += z1 * sB1 + z2 * sB2;
    C += z1 * sC1 + z2 * sC2;
    if (bias) bias += z2 * sBias2;

    const int row0 = blockIdx.y * BM;
    const int col0 = blockIdx.x * BN;
    const int t    = threadIdx.x;
    const int lane = t & 31, wid = t >> 5;
    const int wm = wid & 3, wn = wid >> 2;

    const uint32_t smBase = (uint32_t)__cvta_generic_to_shared(sm);
    const int r8 = t >> 2;
    const int c4 = (t & 3) << 2;

    auto issue = [&](int kt, int s) {
        uint32_t sa_ = smBase + (uint32_t)(s * STAGE) * 4u;
        uint32_t sb_ = sa_ + (uint32_t)(BM * P) * 4u;
        int k0 = kt * BK;
        #pragma unroll
        for (int i = 0; i < 2; i++) {
            int r = r8 + i * 64;
            cpa16(sa_ + (uint32_t)(r * P + c4) * 4u, &A[(long)(row0 + r) * lda + k0 + c4]);
        }
        cpa16(sb_ + (uint32_t)(r8 * P + c4) * 4u, &B[(long)(col0 + r8) * ldb + k0 + c4]);
        asm volatile("cp.async.commit_group;");
    };

    float accs[2][4][4];
    #pragma unroll
    for (int mt = 0; mt < 2; mt++)
        #pragma unroll
        for (int nt = 0; nt < 4; nt++)
            #pragma unroll
            for (int i = 0; i < 4; i++) accs[mt][nt][i] = 0.f;

    auto compute = [&](int s) {
        const uint32_t* asp = reinterpret_cast<const uint32_t*>(sm + s * STAGE);
        const uint32_t* bsp = asp + BM * P;
        #pragma unroll
        for (int ks = 0; ks < 2; ks++) {
            uint32_t af[2][4], bf[4][2];
            #pragma unroll
            for (int mt = 0; mt < 2; mt++) {
                int rb = wm * 32 + mt * 16 + (lane >> 2);
                int cb = ks * 8 + (lane & 3);
                af[mt][0] = asp[rb * P + cb];
                af[mt][1] = asp[(rb + 8) * P + cb];
                af[mt][2] = asp[rb * P + cb + 4];
                af[mt][3] = asp[(rb + 8) * P + cb + 4];
            }
            #pragma unroll
            for (int nt = 0; nt < 4; nt++) {
                int nb = wn * 32 + nt * 8 + (lane >> 2);
                int kb = ks * 8 + (lane & 3);
                bf[nt][0] = bsp[nb * P + kb];
                bf[nt][1] = bsp[nb * P + kb + 4];
            }
            #pragma unroll
            for (int mt = 0; mt < 2; mt++)
                #pragma unroll
                for (int nt = 0; nt < 4; nt++) {
                    float* c = accs[mt][nt];
                    asm volatile(
                        "mma.sync.aligned.m16n8k8.row.col.f32.tf32.tf32.f32 "
                        "{%0,%1,%2,%3}, {%4,%5,%6,%7}, {%8,%9}, {%0,%1,%2,%3};"
                        : "+f"(c[0]), "+f"(c[1]), "+f"(c[2]), "+f"(c[3])
                        : "r"(af[mt][0]), "r"(af[mt][1]), "r"(af[mt][2]), "r"(af[mt][3]),
                          "r"(bf[nt][0]), "r"(bf[nt][1]));
                }
        }
    };

    const int tiles = K / BK;
    if (0 < tiles) issue(0, 0);
    if (1 < tiles) issue(1, 1);

    for (int i = 0; i < tiles; i++) {
        if (i + 1 < tiles) asm volatile("cp.async.wait_group 1;");
        else               asm volatile("cp.async.wait_group 0;");
        __syncthreads();
        if (i + 2 < tiles) issue(i + 2, (i + 2) % 3);
        compute(i % 3);
    }

    #pragma unroll
    for (int mt = 0; mt < 2; mt++) {
        #pragma unroll
        for (int nt = 0; nt < 4; nt++) {
            int r = row0 + wm * 32 + mt * 16 + (lane >> 2);
            int c = col0 + wn * 32 + nt * 8 + ((lane & 3) << 1);
            float* acc = accs[mt][nt];
            #pragma unroll
            for (int e = 0; e < 4; e++) {
                int rr = r + (e >> 1) * 8;
                int cc = c + (e & 1);
                float v = acc[e] * alpha;
                if (bias) v += bias[cc];
                if (ACT == 1) v = 0.5f * v * (1.0f + erff(v * 0.70710678118654752f));
                C[(long)rr * ldc + cc] = v;
            }
        }
    }
}

// ---------------------------------------------------------------------------
// TF32 NT GEMM, BN=128, 512 threads (16 warps, 4x4), warp tile 32x32.
// Per-warp accs halve -> 2 CTA/SM = 32 warps/SM for latency hiding.
// ACT: 0 none, 1 GELU, 2 = sim-map epilogue (ordered-uint with mnorm scale).
// ---------------------------------------------------------------------------
template<int ACT>
__global__ void __launch_bounds__(512, 2) tgemm_nt128(
    const float* __restrict__ A, const float* __restrict__ B,
    const float* __restrict__ bias, float* __restrict__ C,
    int R, int Cc, int K, int lda, int ldb, int ldc,
    long sA1, long sA2, long sB1, long sB2, long sC1, long sC2, long sBias2,
    int Z2, float alpha)
{
    constexpr int BM = 128, BN = 128, BK = 16, P = 20;
    constexpr int STAGE = (BM + BN) * P;   // 5120 floats
    __shared__ float sm[3 * STAGE];        // 61440 B

    const int z  = blockIdx.z;
    const int z1 = z / Z2, z2 = z % Z2;
    A += z1 * sA1 + z2 * sA2;
    B += z1 * sB1 + z2 * sB2;
    C += z1 * sC1 + z2 * sC2;
    if (bias) bias += z2 * sBias2;

    const int row0 = blockIdx.y * BM;
    const int col0 = blockIdx.x * BN;
    const int t    = threadIdx.x;
    const int lane = t & 31, wid = t >> 5;   // wid 0..15
    const int wm = wid & 3, wn = wid >> 2;   // 4 x 4 warps

    const uint32_t smBase = (uint32_t)__cvta_generic_to_shared(sm);
    const int r8 = t >> 2;            // 0..127
    const int c4 = (t & 3) << 2;

    auto issue = [&](int kt, int s) {
        uint32_t sa_ = smBase + (uint32_t)(s * STAGE) * 4u;
        uint32_t sb_ = sa_ + (uint32_t)(BM * P) * 4u;
        int k0 = kt * BK;
        cpa16(sa_ + (uint32_t)(r8 * P + c4) * 4u, &A[(long)(row0 + r8) * lda + k0 + c4]);
        cpa16(sb_ + (uint32_t)(r8 * P + c4) * 4u, &B[(long)(col0 + r8) * ldb + k0 + c4]);
        asm volatile("cp.async.commit_group;");
    };

    float accs[2][4][4];
    #pragma unroll
    for (int mt = 0; mt < 2; mt++)
        #pragma unroll
        for (int nt = 0; nt < 4; nt++)
            #pragma unroll
            for (int i = 0; i < 4; i++) accs[mt][nt][i] = 0.f;

    auto compute = [&](int s) {
        const uint32_t* asp = reinterpret_cast<const uint32_t*>(sm + s * STAGE);
        const uint32_t* bsp = asp + BM * P;
        #pragma unroll
        for (int ks = 0; ks < 2; ks++) {
            uint32_t af[2][4], bf[4][2];
            #pragma unroll
            for (int mt = 0; mt < 2; mt++) {
                int rb = wm * 32 + mt * 16 + (lane >> 2);
                int cb = ks * 8 + (lane & 3);
                af[mt][0] = asp[rb * P + cb];
                af[mt][1] = asp[(rb + 8) * P + cb];
                af[mt][2] = asp[rb * P + cb + 4];
                af[mt][3] = asp[(rb + 8) * P + cb + 4];
            }
            #pragma unroll
            for (int nt = 0; nt < 4; nt++) {
                int nb = wn * 32 + nt * 8 + (lane >> 2);
                int kb = ks * 8 + (lane & 3);
                bf[nt][0] = bsp[nb * P + kb];
                bf[nt][1] = bsp[nb * P + kb + 4];
            }
            #pragma unroll
            for (int mt = 0; mt < 2; mt++)
                #pragma unroll
                for (int nt = 0; nt < 4; nt++) {
                    float* c = accs[mt][nt];
                    asm volatile(
                        "mma.sync.aligned.m16n8k8.row.col.f32.tf32.tf32.f32 "
                        "{%0,%1,%2,%3}, {%4,%5,%6,%7}, {%8,%9}, {%0,%1,%2,%3};"
                        : "+f"(c[0]), "+f"(c[1]), "+f"(c[2]), "+f"(c[3])
                        : "r"(af[mt][0]), "r"(af[mt][1]), "r"(af[mt][2]), "r"(af[mt][3]),
                          "r"(bf[nt][0]), "r"(bf[nt][1]));
                }
        }
    };

    const int tiles = K / BK;
    if (0 < tiles) issue(0, 0);
    if (1 < tiles) issue(1, 1);

    for (int i = 0; i < tiles; i++) {
        if (i + 1 < tiles) asm volatile("cp.async.wait_group 1;");
        else               asm volatile("cp.async.wait_group 0;");
        __syncthreads();
        if (i + 2 < tiles) issue(i + 2, (i + 2) % 3);
        compute(i % 3);
    }

    #pragma unroll
    for (int mt = 0; mt < 2; mt++) {
        #pragma unroll
        for (int nt = 0; nt < 4; nt++) {
            int r = row0 + wm * 32 + mt * 16 + (lane >> 2);
            int c = col0 + wn * 32 + nt * 8 + ((lane & 3) << 1);
            float* acc = accs[mt][nt];
            #pragma unroll
            for (int e = 0; e < 4; e++) {
                int rr = r + (e >> 1) * 8;
                int cc = c + (e & 1);
                if (ACT == 2) {
                    float v = acc[e] * bias[(long)cc * BSZ];
                    reinterpret_cast<uint32_t*>(C)[(long)rr * ldc + cc] = ordermap(v);
                } else {
                    float v = acc[e] * alpha;
                    if (bias) v += bias[cc];
                    if (ACT == 1) v = 0.5f * v * (1.0f + erff(v * 0.70710678118654752f));
                    C[(long)rr * ldc + cc] = v;
                }
            }
        }
    }
}

// ---------------------------------------------------------------------------
// Radix-select top-CAND candidates per (n,b) from pre-mapped uint keys.
// ---------------------------------------------------------------------------
__global__ void __launch_bounds__(256) topk_radix(
    const uint32_t* __restrict__ usim, int* __restrict__ cand)
{
    int n = blockIdx.x, b = blockIdx.y;
    const uint32_t* row = usim + ((long)b * NP + n) * MNP;
    int t = threadIdx.x, w = t >> 5, lane = t & 31;

    __shared__ uint32_t sv[MNP];
    __shared__ uint32_t hist[8][264];
    __shared__ uint32_t wsum[8];
    __shared__ uint32_t sh_prefix, sh_needed, sh_cnt, sh_ecnt;
    __shared__ int elist[CAND];

    #pragma unroll
    for (int j = 0; j < MNP / 1024; j++) {
        int m4 = t + j * 256;
        *reinterpret_cast<uint4*>(&sv[m4 * 4]) =
            *reinterpret_cast<const uint4*>(&row[m4 * 4]);
    }

    uint32_t prefix = 0, pmask = 0;
    int needed = CAND;

    #pragma unroll
    for (int shift = 24; shift >= 0; shift -= 8) {
        #pragma unroll
        for (int i = 0; i < 8; i++) hist[i][t] = 0;
        __syncthreads();

        #pragma unroll
        for (int j = 0; j < MNP / 256; j++) {
            uint32_t u = sv[t + j * 256];
            if ((u & pmask) == prefix)
                atomicAdd(&hist[w][(u >> shift) & 255u], 1u);
        }
        __syncthreads();

        uint32_t cnt0 = 0;
        #pragma unroll
        for (int k = 0; k < 8; k++) cnt0 += hist[k][t];

        uint32_t c = cnt0;
        #pragma unroll
        for (int off = 1; off < 32; off <<= 1) {
            uint32_t v = __shfl_down_sync(0xffffffffu, c, off);
            if (lane + off < 32) c += v;
        }
        if (lane == 0) wsum[w] = c;
        __syncthreads();
        uint32_t wsuf = 0;
        #pragma unroll
        for (int k = 0; k < 8; k++) if (k > w) wsuf += wsum[k];
        uint32_t suf = c + wsuf;
        uint32_t above = suf - cnt0;

        if ((int)above < needed && (int)suf >= needed) {
            sh_prefix = prefix | ((uint32_t)t << shift);
            sh_needed = (uint32_t)(needed - (int)above);
        }
        __syncthreads();
        prefix = sh_prefix;
        needed = (int)sh_needed;
        pmask |= (0xFFu << shift);
        __syncthreads();
    }

    if (t == 0) { sh_cnt = 0; sh_ecnt = 0; }
    __syncthreads();

    const uint32_t T = prefix;
    const int rem = needed;
    int* out = cand + ((long)b * NP + n) * CAND;

    #pragma unroll
    for (int j = 0; j < MNP / 256; j++) {
        int m = t + j * 256;
        uint32_t u = sv[m];
        if (u > T) {
            int pos = (int)atomicAdd(&sh_cnt, 1u);
            out[pos] = m;
        } else if (u == T) {
            int ep = (int)atomicAdd(&sh_ecnt, 1u);
            if (ep < CAND) elist[ep] = m;
        }
    }
    __syncthreads();

    if (t == 0) {
        int base = (int)sh_cnt;
        int ec = (int)sh_ecnt; if (ec > CAND) ec = CAND;
        int last = -1;
        for (int i = 0; i < rem; i++) {
            int best = 0x7fffffff;
            for (int j = 0; j < ec; j++) {
                int v = elist[j];
                if (v > last && v < best) best = v;
            }
            out[base + i] = best;
            last = best;
        }
    }
}

// ---------------------------------------------------------------------------
// Exact fp32 rescoring of CAND candidates per (n,b); select exact top-32.
// ---------------------------------------------------------------------------
__global__ void __launch_bounds__(256) rescore_kernel(
    const float* __restrict__ tgt, const float* __restrict__ memory,
    const float* __restrict__ mnorm, const int* __restrict__ cand,
    int* __restrict__ rns)
{
    int n = blockIdx.x, b = blockIdx.y;
    int t = threadIdx.x, w = t >> 5, lane = t & 31;
    __shared__ int   cidx[CAND];
    __shared__ float csc[CAND];
    __shared__ uint32_t cnt;

    if (t < CAND) cidx[t] = cand[((long)b * NP + n) * CAND + t];
    if (t == 0) cnt = 0;
    __syncthreads();

    const float* trow = tgt + ((long)n * BSZ + b) * DIM;
    #pragma unroll
    for (int j = 0; j < CAND / 8; j++) {
        int ci = w * (CAND / 8) + j;
        int m = cidx[ci];
        const float* mrow = memory + ((long)m * BSZ + b) * DIM;
        float s = 0.f;
        #pragma unroll
        for (int i = 0; i < 2; i++) {
            int d = lane * 4 + i * 128;
            float4 a = *reinterpret_cast<const float4*>(trow + d);
            float4 v = *reinterpret_cast<const float4*>(mrow + d);
            s = fmaf(a.x, v.x, s); s = fmaf(a.y, v.y, s);
            s = fmaf(a.z, v.z, s); s = fmaf(a.w, v.w, s);
        }
        #pragma unroll
        for (int o = 16; o; o >>= 1) s += __shfl_xor_sync(0xffffffffu, s, o);
        if (lane == 0) csc[ci] = s * mnorm[(long)m * BSZ + b];
    }
    __syncthreads();

    if (t < CAND) {
        float sc = csc[t]; int mi = cidx[t];
        int rank = 0;
        #pragma unroll
        for (int k = 0; k < CAND; k++) {
            float so = csc[k]; int mo = cidx[k];
            if (so > sc || (so == sc && mo < mi)) rank++;
        }
        if (rank < TOPK) {
            int pos = (int)atomicAdd(&cnt, 1u);
            rns[((long)b * NP + n) * TOPK + pos] = mi;
        }
    }
}

// ---------------------------------------------------------------------------
// Fused sparse cross-attention + LN1 + qadd=t1+qpos
// ---------------------------------------------------------------------------
__global__ void cross_ln_kernel(const float* __restrict__ Q,
                                const float* __restrict__ Kb,
                                const float* __restrict__ Vb,
                                const int*   __restrict__ rns,
                                const float* __restrict__ tgt,
                                const float* __restrict__ w,
                                const float* __restrict__ beta,
                                const float* __restrict__ qpos,
                                float* __restrict__ t1,
                                float* __restrict__ qadd)
{
    int n = blockIdx.x, b = blockIdx.y;
    int t = threadIdx.x, h = t >> 5, lane = t & 31;
    __shared__ int idx[TOPK];
    __shared__ float red[8];
    if (t < TOPK) idx[t] = rns[((long)b * NP + n) * TOPK + t];
    __syncthreads();

    long rowoff = ((long)n * BSZ + b) * DIM;
    float q = Q[rowoff + h * HD + lane];

    float myscore = -INFINITY;
    #pragma unroll
    for (int j = 0; j < TOPK; j++) {
        float prod = q * Kb[((long)idx[j] * BSZ + b) * DIM + h * HD + lane];
        #pragma unroll
        for (int o = 16; o; o >>= 1) prod += __shfl_xor_sync(0xffffffffu, prod, o);
        if (lane == j) myscore = prod * ATT_SCALE;
    }
    float mx = myscore;
    #pragma unroll
    for (int o = 16; o; o >>= 1) mx = fmaxf(mx, __shfl_xor_sync(0xffffffffu, mx, o));
    float e = expf(myscore - mx);
    float s = e;
    #pragma unroll
    for (int o = 16; o; o >>= 1) s += __shfl_xor_sync(0xffffffffu, s, o);
    float p = e / s;

    float acc = 0.f;
    #pragma unroll
    for (int j = 0; j < TOPK; j++) {
        float pj = __shfl_sync(0xffffffffu, p, j);
        acc = fmaf(pj, Vb[((long)idx[j] * BSZ + b) * DIM + h * HD + lane], acc);
    }

    float x = tgt[rowoff + t] + acc;
    float sum = x;
    #pragma unroll
    for (int o = 16; o; o >>= 1) sum += __shfl_xor_sync(0xffffffffu, sum, o);
    if (lane == 0) red[h] = sum;
    __syncthreads();
    float tot = 0.f;
    #pragma unroll
    for (int k = 0; k < 8; k++) tot += red[k];
    float mu = tot * (1.0f / DIM);
    __syncthreads();

    float d = x - mu;
    float s2 = d * d;
    #pragma unroll
    for (int o = 16; o; o >>= 1) s2 += __shfl_xor_sync(0xffffffffu, s2, o);
    if (lane == 0) red[h] = s2;
    __syncthreads();
    float tot2 = 0.f;
    #pragma unroll
    for (int k = 0; k < 8; k++) tot2 += red[k];
    float var = tot2 * (1.0f / DIM);

    float t1v = d * rsqrtf(var + LN_EPS) * w[t] + beta[t];
    t1[rowoff + t]   = t1v;
    qadd[rowoff + t] = t1v + qpos[rowoff + t];
}

// ---------------------------------------------------------------------------
// Fused flash self-attention
// ---------------------------------------------------------------------------
__global__ void __launch_bounds__(256) flash_sa_kernel(
    const float* __restrict__ QK2, const float* __restrict__ V2,
    float* __restrict__ sa)
{
    constexpr int QP = 36, KP = 36, VP = 36, PP = 36, CH = 32, NCH = NP / CH;
    __shared__ float Qs[128 * QP];
    __shared__ float Ks[CH * KP];
    __shared__ float Vs[HD * VP];
    __shared__ float Ps[128 * PP];

    const int q0 = blockIdx.x * 128;
    const int bh = blockIdx.y;
    const int b  = bh >> 3, h = bh & 7;
    const int t  = threadIdx.x, lane = t & 31, wm = t >> 5;

    {
        int r = t >> 1, c0 = (t & 1) * 16;
        const float* src = QK2 + ((long)(q0 + r) * BSZ + b) * 512 + h * HD + c0;
        #pragma unroll
        for (int i = 0; i < 4; i++)
            *reinterpret_cast<float4*>(&Qs[r * QP + c0 + i * 4]) =
                *reinterpret_cast<const float4*>(src + i * 4);
    }

    float m0 = -INFINITY, m1 = -INFINITY, l0 = 0.f, l1 = 0.f;
    float o[4][4] = {};
    const int rA  = wm * 16 + (lane >> 2);
    const int cq  = lane & 3;

    for (int kt = 0; kt < NCH; kt++) {
        if (t < 64) {
            int r = t >> 1, c0 = (t & 1) * 16;
            const float* src = QK2 + ((long)(kt * CH + r) * BSZ + b) * 512 + DIM + h * HD + c0;
            #pragma unroll
            for (int i = 0; i < 4; i++)
                *reinterpret_cast<float4*>(&Ks[r * KP + c0 + i * 4]) =
                    *reinterpret_cast<const float4*>(src + i * 4);
        } else if (t < 128) {
            int tt = t - 64;
            int key = tt >> 1, c0 = (tt & 1) * 16;
            const float* src = V2 + ((long)(kt * CH + key) * BSZ + b) * DIM + h * HD + c0;
            #pragma unroll
            for (int i = 0; i < 4; i++) {
                float4 v = *reinterpret_cast<const float4*>(src + i * 4);
                Vs[(c0 + i * 4 + 0) * VP + key] = ftf32(v.x);
                Vs[(c0 + i * 4 + 1) * VP + key] = ftf32(v.y);
                Vs[(c0 + i * 4 + 2) * VP + key] = ftf32(v.z);
                Vs[(c0 + i * 4 + 3) * VP + key] = ftf32(v.w);
            }
        }
        __syncthreads();

        float s[4][4];
        #pragma unroll
        for (int nt = 0; nt < 4; nt++)
            #pragma unroll
            for (int e = 0; e < 4; e++) s[nt][e] = 0.f;

        const uint32_t* qsp = reinterpret_cast<const uint32_t*>(Qs);
        const uint32_t* ksp = reinterpret_cast<const uint32_t*>(Ks);
        #pragma unroll
        for (int ks = 0; ks < 4; ks++) {
            int cb = ks * 8 + cq;
            uint32_t a0 = qsp[rA * QP + cb];
            uint32_t a1 = qsp[(rA + 8) * QP + cb];
            uint32_t a2 = qsp[rA * QP + cb + 4];
            uint32_t a3 = qsp[(rA + 8) * QP + cb + 4];
            #pragma unroll
            for (int nt = 0; nt < 4; nt++) {
                int nb = nt * 8 + (lane >> 2);
                uint32_t b0 = ksp[nb * KP + cb];
                uint32_t b1 = ksp[nb * KP + cb + 4];
                float* c = s[nt];
                asm volatile(
                    "mma.sync.aligned.m16n8k8.row.col.f32.tf32.tf32.f32 "
                    "{%0,%1,%2,%3}, {%4,%5,%6,%7}, {%8,%9}, {%0,%1,%2,%3};"
                    : "+f"(c[0]), "+f"(c[1]), "+f"(c[2]), "+f"(c[3])
                    : "r"(a0), "r"(a1), "r"(a2), "r"(a3), "r"(b0), "r"(b1));
            }
        }

        float mxA = -INFINITY, mxB = -INFINITY;
        #pragma unroll
        for (int nt = 0; nt < 4; nt++) {
            #pragma unroll
            for (int e = 0; e < 4; e++) s[nt][e] *= ATT_SCALE;
            mxA = fmaxf(mxA, fmaxf(s[nt][0], s[nt][1]));
            mxB = fmaxf(mxB, fmaxf(s[nt][2], s[nt][3]));
        }
        #pragma unroll
        for (int off = 1; off <= 2; off <<= 1) {
            mxA = fmaxf(mxA, __shfl_xor_sync(0xffffffffu, mxA, off));
            mxB = fmaxf(mxB, __shfl_xor_sync(0xffffffffu, mxB, off));
        }
        float mA = fmaxf(m0, mxA), mB = fmaxf(m1, mxB);
        float sc0 = expf(m0 - mA), sc1 = expf(m1 - mB);

        float sumA = 0.f, sumB = 0.f;
        float pr[4][4];
        #pragma unroll
        for (int nt = 0; nt < 4; nt++) {
            pr[nt][0] = expf(s[nt][0] - mA);
            pr[nt][1] = expf(s[nt][1] - mA);
            pr[nt][2] = expf(s[nt][2] - mB);
            pr[nt][3] = expf(s[nt][3] - mB);
            sumA += pr[nt][0] + pr[nt][1];
            sumB += pr[nt][2] + pr[nt][3];
        }
        #pragma unroll
        for (int off = 1; off <= 2; off <<= 1) {
            sumA += __shfl_xor_sync(0xffffffffu, sumA, off);
            sumB += __shfl_xor_sync(0xffffffffu, sumB, off);
        }
        l0 = l0 * sc0 + sumA;
        l1 = l1 * sc1 + sumB;
        m0 = mA; m1 = mB;

        #pragma unroll
        for (int nt = 0; nt < 4; nt++) {
            float2 pa = make_float2(ftf32(pr[nt][0]), ftf32(pr[nt][1]));
            float2 pb = make_float2(ftf32(pr[nt][2]), ftf32(pr[nt][3]));
            *reinterpret_cast<float2*>(&Ps[rA * PP + nt * 8 + cq * 2]) = pa;
            *reinterpret_cast<float2*>(&Ps[(rA + 8) * PP + nt * 8 + cq * 2]) = pb;
        }
        __syncwarp();

        #pragma unroll
        for (int nt = 0; nt < 4; nt++) {
            o[nt][0] *= sc0; o[nt][1] *= sc0;
            o[nt][2] *= sc1; o[nt][3] *= sc1;
        }
        const uint32_t* psp = reinterpret_cast<const uint32_t*>(Ps);
        const uint32_t* vsp = reinterpret_cast<const uint32_t*>(Vs);
        #pragma unroll
        for (int ks = 0; ks < 4; ks++) {
            int cb = ks * 8 + cq;
            uint32_t a0 = psp[rA * PP + cb];
            uint32_t a1 = psp[(rA + 8) * PP + cb];
            uint32_t a2 = psp[rA * PP + cb + 4];
            uint32_t a3 = psp[(rA + 8) * PP + cb + 4];
            #pragma unroll
            for (int nt = 0; nt < 4; nt++) {
                int nb = nt * 8 + (lane >> 2);
                uint32_t b0 = vsp[nb * VP + cb];
                uint32_t b1 = vsp[nb * VP + cb + 4];
                float* c = o[nt];
                asm volatile(
                    "mma.sync.aligned.m16n8k8.row.col.f32.tf32.tf32.f32 "
                    "{%0,%1,%2,%3}, {%4,%5,%6,%7}, {%8,%9}, {%0,%1,%2,%3};"
                    : "+f"(c[0]), "+f"(c[1]), "+f"(c[2]), "+f"(c[3])
                    : "r"(a0), "r"(a1), "r"(a2), "r"(a3), "r"(b0), "r"(b1));
            }
        }
        __syncthreads();
    }

    float i0 = 1.f / l0, i1 = 1.f / l1;
    #pragma unroll
    for (int nt = 0; nt < 4; nt++) {
        int col = h * HD + nt * 8 + cq * 2;
        long rowA = (long)(q0 + rA) * BSZ + b;
        long rowB = (long)(q0 + rA + 8) * BSZ + b;
        *reinterpret_cast<float2*>(&sa[rowA * DIM + col]) =
            make_float2(o[nt][0] * i0, o[nt][1] * i0);
        *reinterpret_cast<float2*>(&sa[rowB * DIM + col]) =
            make_float2(o[nt][2] * i1, o[nt][3] * i1);
    }
}

// ---------------------------------------------------------------------------
// out = LayerNorm(a + c) * w + beta
// ---------------------------------------------------------------------------
__global__ void add_ln_kernel(const float* __restrict__ a, const float* __restrict__ c,
                              const float* __restrict__ w, const float* __restrict__ beta,
                              float* __restrict__ out)
{
    long r = blockIdx.x;
    int  t = threadIdx.x;
    float x = a[r * DIM + t] + c[r * DIM + t];
    __shared__ float red[8];

    float s = x;
    #pragma unroll
    for (int o = 16; o; o >>= 1) s += __shfl_xor_sync(0xffffffffu, s, o);
    if ((t & 31) == 0) red[t >> 5] = s;
    __syncthreads();
    float tot = 0.f;
    #pragma unroll
    for (int k = 0; k < 8; k++) tot += red[k];
    float mu = tot * (1.0f / DIM);
    __syncthreads();

    float d  = x - mu;
    float s2 = d * d;
    #pragma unroll
    for (int o = 16; o; o >>= 1) s2 += __shfl_xor_sync(0xffffffffu, s2, o);
    if ((t & 31) == 0) red[t >> 5] = s2;
    __syncthreads();
    float tot2 = 0.f;
    #pragma unroll
    for (int k = 0; k < 8; k++) tot2 += red[k];
    float var = tot2 * (1.0f / DIM);

    out[r * DIM + t] = d * rsqrtf(var + LN_EPS) * w[t] + beta[t];
}

// ---------------------------------------------------------------------------
// out = LN(t2 + p0 + p1 + p2 + p3 + bias)
// ---------------------------------------------------------------------------
__global__ void ln3_fused_kernel(const float* __restrict__ t2,
                                 const float* __restrict__ pp,
                                 long pstride,
                                 const float* __restrict__ bias,
                                 const float* __restrict__ w,
                                 const float* __restrict__ beta,
                                 float* __restrict__ out)
{
    long r = blockIdx.x;
    int  t = threadIdx.x;
    long o4 = r * DIM + t;
    float x = t2[o4] + ((pp[o4] + pp[o4 + pstride]) +
                        (pp[o4 + 2 * pstride] + pp[o4 + 3 * pstride]) + bias[t]);
    __shared__ float red[8];

    float s = x;
    #pragma unroll
    for (int o = 16; o; o >>= 1) s += __shfl_xor_sync(0xffffffffu, s, o);
    if ((t & 31) == 0) red[t >> 5] = s;
    __syncthreads();
    float tot = 0.f;
    #pragma unroll
    for (int k = 0; k < 8; k++) tot += red[k];
    float mu = tot * (1.0f / DIM);
    __syncthreads();

    float d  = x - mu;
    float s2 = d * d;
    #pragma unroll
    for (int o = 16; o; o >>= 1) s2 += __shfl_xor_sync(0xffffffffu, s2, o);
    if ((t & 31) == 0) red[t >> 5] = s2;
    __syncthreads();
    float tot2 = 0.f;
    #pragma unroll
    for (int k = 0; k < 8; k++) tot2 += red[k];
    float var = tot2 * (1.0f / DIM);

    out[r * DIM + t] = d * rsqrtf(var + LN_EPS) * w[t] + beta[t];
}

// ---------------------------------------------------------------------------
// Launch
// ---------------------------------------------------------------------------
extern "C" void kernel_launch(void* const* d_in, const int* in_sizes, int n_in,
                              void* d_out, int out_size)
{
    const float* tgt      = (const float*)d_in[0];
    const float* memory   = (const float*)d_in[1];
    const float* qpos     = (const float*)d_in[2];
    const float* kpos     = (const float*)d_in[3];
    const float* cw1      = (const float*)d_in[4];
    const float* cb1      = (const float*)d_in[5];
    const float* cw2      = (const float*)d_in[6];
    const float* cb2      = (const float*)d_in[7];
    const float* cw3      = (const float*)d_in[8];
    const float* cb3      = (const float*)d_in[9];
    const float* sa_in_w  = (const float*)d_in[10];
    const float* sa_in_b  = (const float*)d_in[11];
    const float* sa_out_w = (const float*)d_in[12];
    const float* sa_out_b = (const float*)d_in[13];
    const float* ln1_w    = (const float*)d_in[14];
    const float* ln1_b    = (const float*)d_in[15];
    const float* ln2_w    = (const float*)d_in[16];
    const float* ln2_b    = (const float*)d_in[17];
    const float* ln3_w    = (const float*)d_in[18];
    const float* ln3_b    = (const float*)d_in[19];
    const float* ff1_w    = (const float*)d_in[20];
    const float* ff1_b    = (const float*)d_in[21];
    const float* ff2_w    = (const float*)d_in[22];
    const float* ff2_b    = (const float*)d_in[23];
    float* out = (float*)d_out;

    void *p;
    cudaGetSymbolAddress(&p, g_usim);  uint32_t* usim = (uint32_t*)p;
    cudaGetSymbolAddress(&p, g_mnorm); float* mnorm = (float*)p;
    cudaGetSymbolAddress(&p, g_cand);  int*   cand  = (int*)p;
    cudaGetSymbolAddress(&p, g_rns);   int*   rns   = (int*)p;
    cudaGetSymbolAddress(&p, g_K);     float* Kb    = (float*)p;
    cudaGetSymbolAddress(&p, g_V);     float* Vb    = (float*)p;
    cudaGetSymbolAddress(&p, g_Q);     float* Qb    = (float*)p;
    cudaGetSymbolAddress(&p, g_t1);    float* t1    = (float*)p;
    cudaGetSymbolAddress(&p, g_QK2);   float* QK2   = (float*)p;
    cudaGetSymbolAddress(&p, g_V2);    float* V2    = (float*)p;
    cudaGetSymbolAddress(&p, g_sa);    float* sa    = (float*)p;
    cudaGetSymbolAddress(&p, g_sa2);   float* sa2   = (float*)p;
    cudaGetSymbolAddress(&p, g_t2);    float* t2    = (float*)p;
    cudaGetSymbolAddress(&p, g_ffh);   float* ffh   = (float*)p;
    cudaGetSymbolAddress(&p, g_ffo);   float* ffo   = (float*)p;
    cudaGetSymbolAddress(&p, g_madd);  float* madd  = (float*)p;
    cudaGetSymbolAddress(&p, g_qadd);  float* qadd  = (float*)p;

    const int BD = BSZ * DIM;   // 2048
    const int NB = NP * BSZ;    // 4096
    const int MB = MNP * BSZ;   // 32768

    // 1) fused pre: madd, mnorm, qadd
    pre_kernel<<<MB / 8 + NB * DIM / 4096, 256>>>(memory, kpos, madd, mnorm, tgt, qpos, qadd);

    // 2) sim (BN=128 @ 512 threads, ordermap epilogue with mnorm)
    tgemm_nt128<2><<<dim3(MNP / 128, NP / 128, BSZ), 512>>>(
        tgt, memory, mnorm, (float*)usim,
        NP, MNP, DIM, BD, BD, MNP,
        0, DIM, 0, DIM, 0, (long)NP * MNP, 1, BSZ, 1.0f);

    // 3) radix top-48 candidates
    topk_radix<<<dim3(NP, BSZ), 256>>>(usim, cand);

    // 4) exact fp32 rescore -> exact top-32
    rescore_kernel<<<dim3(NP, BSZ), 256>>>(tgt, memory, mnorm, cand, rns);

    // 5) K + V projections, BN=128 @ 512 threads, ONE launch
    tgemm_nt128<0><<<dim3(DIM / 128, MB / 128, 2), 512>>>(
        madd, cw2, cb2, Kb,
        MB, DIM, DIM, DIM, DIM, DIM,
        0, (long)(memory - madd),
        0, (long)(cw3 - cw2),
        0, (long)(Vb - Kb),
        (long)(cb3 - cb2), 2, 1.0f);
    // Q projection (small grid, BN=64)
    tgemm_nt64<0><<<dim3(DIM / 64, NB / 128, 1), 256>>>(
        qadd, cw1, cb1, Qb, NB, DIM, DIM, DIM, DIM, DIM, 0, 0, 0, 0, 0, 0, 0, 1, 1.0f);

    // 6) cross-attention + LN1 + (qadd = t1 + qpos)
    cross_ln_kernel<<<dim3(NP, BSZ), 256>>>(Qb, Kb, Vb, rns, tgt, ln1_w, ln1_b, qpos, t1, qadd);

    // 7) self-attn projections
    tgemm_nt64<0><<<dim3(2 * DIM / 64, NB / 128, 1), 256>>>(
        qadd, sa_in_w, sa_in_b, QK2, NB, 2 * DIM, DIM, DIM, DIM, 2 * DIM, 0, 0, 0, 0, 0, 0, 0, 1, 1.0f);
    tgemm_nt64<0><<<dim3(DIM / 64, NB / 128, 1), 256>>>(
        t1, sa_in_w + 2 * DIM * DIM, sa_in_b + 2 * DIM, V2,
        NB, DIM, DIM, DIM, DIM, DIM, 0, 0, 0, 0, 0, 0, 0, 1, 1.0f);

    // 8) flash self-attention
    flash_sa_kernel<<<dim3(NP / 128, BSZ * NH), 256>>>(QK2, V2, sa);

    // 9) out projection, t2 = LN(t1 + sa2)
    tgemm_nt64<0><<<dim3(DIM / 64, NB / 128, 1), 256>>>(
        sa, sa_out_w, sa_out_b, sa2, NB, DIM, DIM, DIM, DIM, DIM, 0, 0, 0, 0, 0, 0, 0, 1, 1.0f);
    add_ln_kernel<<<NB, 256>>>(t1, sa2, ln2_w, ln2_b, t2);

    // 10) FFN1 (GELU, BN=128 @ 512 threads)
    tgemm_nt128<1><<<dim3(FF / 128, NB / 128, 1), 512>>>(
        t2, ff1_w, ff1_b, ffh, NB, FF, DIM, DIM, DIM, FF, 0, 0, 0, 0, 0, 0, 0, 1, 1.0f);
    // 11) FFN2 split-K=4
    tgemm_nt64<0><<<dim3(DIM / 64, NB / 128, 4), 256>>>(
        ffh, ff2_w, nullptr, ffo, NB, DIM, FF / 4, FF, FF, DIM,
        0, FF / 4, 0, FF / 4, 0, (long)NB * DIM, 0, 4, 1.0f);
    // 12) final fused reduce(4) + LN
    ln3_fused_kernel<<<NB, 256>>>(t2, ffo, (long)NB * DIM, ff2_b, ln3_w, ln3_b, out);
}

// round 17
// speedup vs baseline: 1.0220x; 1.0220x over previous
#include <cuda_runtime.h>
#include <cuda_bf16.h>
#include <math.h>
#include <stdint.h>

#define NP   512
#define MNP  4096
#define BSZ  8
#define DIM  256
#define NH   8
#define TOPK 32
#define CAND 48
#define FF   2048
#define HD   32
#define LN_EPS 1e-5f
#define ATT_SCALE 0.17677669529663687f   /* 1/sqrt(32) */

// ---------------------------------------------------------------------------
// Scratch
// ---------------------------------------------------------------------------
__device__ uint32_t g_usim [BSZ * NP * MNP];
__device__ float g_mnorm [MNP * BSZ];
__device__ int   g_cand  [BSZ * NP * CAND];
__device__ int   g_rns   [BSZ * NP * TOPK];
__device__ float g_K     [MNP * BSZ * DIM];
__device__ float g_V     [MNP * BSZ * DIM];
__device__ float g_Q     [NP * BSZ * DIM];
__device__ float g_t1    [NP * BSZ * DIM];
__device__ float g_QK2   [NP * BSZ * 2 * DIM];
__device__ float g_V2    [NP * BSZ * DIM];
__device__ float g_sa    [NP * BSZ * DIM];
__device__ float g_sa2   [NP * BSZ * DIM];
__device__ float g_t2    [NP * BSZ * DIM];
__device__ float g_ffh   [NP * BSZ * FF];
__device__ float g_ffo   [4 * NP * BSZ * DIM];
__device__ float g_madd  [MNP * BSZ * DIM];
__device__ float g_qadd  [NP * BSZ * DIM];

__device__ __forceinline__ float ftf32(float x) {
    uint32_t u;
    asm("cvt.rna.tf32.f32 %0, %1;" : "=r"(u) : "f"(x));
    return __uint_as_float(u);
}
__device__ __forceinline__ void cpa16(uint32_t dst, const float* src) {
    asm volatile("cp.async.cg.shared.global [%0], [%1], 16;" :: "r"(dst), "l"(src));
}
__device__ __forceinline__ uint32_t ordermap(float v) {
    uint32_t u = __float_as_uint(v);
    return (u & 0x80000000u) ? ~u : (u | 0x80000000u);
}

// ---------------------------------------------------------------------------
// Fused pre: madd = memory+kpos, mnorm, qadd = tgt+qpos
// ---------------------------------------------------------------------------
__global__ void pre_kernel(const float* __restrict__ mem, const float* __restrict__ kp,
                           float* __restrict__ madd, float* __restrict__ mnorm,
                           const float* __restrict__ tg, const float* __restrict__ qp,
                           float* __restrict__ qadd)
{
    const int MBROWS = MNP * BSZ;
    int blk = blockIdx.x;
    int t = threadIdx.x;
    if (blk < MBROWS / 8) {
        int w = t >> 5, lane = t & 31;
        long r = (long)blk * 8 + w;
        const float* src = mem + r * DIM;
        const float* kpr = kp + r * DIM;
        float* dst = madd + r * DIM;
        float s = 0.f;
        #pragma unroll
        for (int i = 0; i < 2; i++) {
            int d = lane * 4 + i * 128;
            float4 v = *reinterpret_cast<const float4*>(src + d);
            s = fmaf(v.x, v.x, s); s = fmaf(v.y, v.y, s);
            s = fmaf(v.z, v.z, s); s = fmaf(v.w, v.w, s);
            float4 k = *reinterpret_cast<const float4*>(kpr + d);
            v.x += k.x; v.y += k.y; v.z += k.z; v.w += k.w;
            *reinterpret_cast<float4*>(dst + d) = v;
        }
        #pragma unroll
        for (int o = 16; o; o >>= 1) s += __shfl_xor_sync(0xffffffffu, s, o);
        if (lane == 0) mnorm[r] = 1.0f / sqrtf(s);
    } else {
        int i = (blk - MBROWS / 8) * 1024 + t;
        #pragma unroll
        for (int j = 0; j < 4; j++) {
            int e = i + j * 256;
            float4 x = ((const float4*)tg)[e];
            float4 y = ((const float4*)qp)[e];
            x.x += y.x; x.y += y.y; x.z += y.z; x.w += y.w;
            ((float4*)qadd)[e] = x;
        }
    }
}

// ---------------------------------------------------------------------------
// TF32 tensor-core NT GEMM, cp.async 3-stage pipeline, 1 barrier/k-tile.
// 256 threads. BN: 64 (3 CTA/SM) or 128 (2 CTA/SM).
// ACT: 0 none, 1 GELU, 2 = sim-map epilogue (ordered-uint with mnorm scale).
// ---------------------------------------------------------------------------
template<int BN, int ACT>
__global__ void __launch_bounds__(256, (BN == 64) ? 3 : 2) tgemm_nt(
    const float* __restrict__ A, const float* __restrict__ B,
    const float* __restrict__ bias, float* __restrict__ C,
    int R, int Cc, int K, int lda, int ldb, int ldc,
    long sA1, long sA2, long sB1, long sB2, long sC1, long sC2, long sBias2,
    int Z2, float alpha)
{
    constexpr int BM = 128, BK = 16, P = 20;
    constexpr int STAGE = (BM + BN) * P;
    constexpr int NT = BN / 16;
    __shared__ float sm[3 * STAGE];

    const int z  = blockIdx.z;
    const int z1 = z / Z2, z2 = z % Z2;
    A += z1 * sA1 + z2 * sA2;
    B += z1 * sB1 + z2 * sB2;
    C += z1 * sC1 + z2 * sC2;
    if (bias) bias += z2 * sBias2;

    const int row0 = blockIdx.y * BM;
    const int col0 = blockIdx.x * BN;
    const int t    = threadIdx.x;
    const int lane = t & 31, wid = t >> 5;
    const int wm = wid & 3, wn = wid >> 2;

    const uint32_t smBase = (uint32_t)__cvta_generic_to_shared(sm);
    const int r8 = t >> 2;
    const int c4 = (t & 3) << 2;

    auto issue = [&](int kt, int s) {
        uint32_t sa_ = smBase + (uint32_t)(s * STAGE) * 4u;
        uint32_t sb_ = sa_ + (uint32_t)(BM * P) * 4u;
        int k0 = kt * BK;
        #pragma unroll
        for (int i = 0; i < 2; i++) {
            int r = r8 + i * 64;
            cpa16(sa_ + (uint32_t)(r * P + c4) * 4u, &A[(long)(row0 + r) * lda + k0 + c4]);
        }
        #pragma unroll
        for (int i = 0; i < BN / 64; i++) {
            int r = r8 + i * 64;
            cpa16(sb_ + (uint32_t)(r * P + c4) * 4u, &B[(long)(col0 + r) * ldb + k0 + c4]);
        }
        asm volatile("cp.async.commit_group;");
    };

    float accs[2][NT][4];
    #pragma unroll
    for (int mt = 0; mt < 2; mt++)
        #pragma unroll
        for (int nt = 0; nt < NT; nt++)
            #pragma unroll
            for (int i = 0; i < 4; i++) accs[mt][nt][i] = 0.f;

    auto compute = [&](int s) {
        const uint32_t* asp = reinterpret_cast<const uint32_t*>(sm + s * STAGE);
        const uint32_t* bsp = asp + BM * P;
        #pragma unroll
        for (int ks = 0; ks < 2; ks++) {
            uint32_t af[2][4], bf[NT][2];
            #pragma unroll
            for (int mt = 0; mt < 2; mt++) {
                int rb = wm * 32 + mt * 16 + (lane >> 2);
                int cb = ks * 8 + (lane & 3);
                af[mt][0] = asp[rb * P + cb];
                af[mt][1] = asp[(rb + 8) * P + cb];
                af[mt][2] = asp[rb * P + cb + 4];
                af[mt][3] = asp[(rb + 8) * P + cb + 4];
            }
            #pragma unroll
            for (int nt = 0; nt < NT; nt++) {
                int nb = wn * (BN / 2) + nt * 8 + (lane >> 2);
                int kb = ks * 8 + (lane & 3);
                bf[nt][0] = bsp[nb * P + kb];
                bf[nt][1] = bsp[nb * P + kb + 4];
            }
            #pragma unroll
            for (int mt = 0; mt < 2; mt++)
                #pragma unroll
                for (int nt = 0; nt < NT; nt++) {
                    float* c = accs[mt][nt];
                    asm volatile(
                        "mma.sync.aligned.m16n8k8.row.col.f32.tf32.tf32.f32 "
                        "{%0,%1,%2,%3}, {%4,%5,%6,%7}, {%8,%9}, {%0,%1,%2,%3};"
                        : "+f"(c[0]), "+f"(c[1]), "+f"(c[2]), "+f"(c[3])
                        : "r"(af[mt][0]), "r"(af[mt][1]), "r"(af[mt][2]), "r"(af[mt][3]),
                          "r"(bf[nt][0]), "r"(bf[nt][1]));
                }
        }
    };

    const int tiles = K / BK;
    if (0 < tiles) issue(0, 0);
    if (1 < tiles) issue(1, 1);

    for (int i = 0; i < tiles; i++) {
        if (i + 1 < tiles) asm volatile("cp.async.wait_group 1;");
        else               asm volatile("cp.async.wait_group 0;");
        __syncthreads();
        if (i + 2 < tiles) issue(i + 2, (i + 2) % 3);
        compute(i % 3);
    }

    #pragma unroll
    for (int mt = 0; mt < 2; mt++) {
        #pragma unroll
        for (int nt = 0; nt < NT; nt++) {
            int r = row0 + wm * 32 + mt * 16 + (lane >> 2);
            int c = col0 + wn * (BN / 2) + nt * 8 + ((lane & 3) << 1);
            float* acc = accs[mt][nt];
            #pragma unroll
            for (int e = 0; e < 4; e++) {
                int rr = r + (e >> 1) * 8;
                int cc = c + (e & 1);
                if (ACT == 2) {
                    float v = acc[e] * bias[(long)cc * BSZ];
                    reinterpret_cast<uint32_t*>(C)[(long)rr * ldc + cc] = ordermap(v);
                } else {
                    float v = acc[e] * alpha;
                    if (bias) v += bias[cc];
                    if (ACT == 1) v = 0.5f * v * (1.0f + erff(v * 0.70710678118654752f));
                    C[(long)rr * ldc + cc] = v;
                }
            }
        }
    }
}

// ---------------------------------------------------------------------------
// Radix-select top-CAND candidates per (n,b) from pre-mapped uint keys.
// ---------------------------------------------------------------------------
__global__ void __launch_bounds__(256) topk_radix(
    const uint32_t* __restrict__ usim, int* __restrict__ cand)
{
    int n = blockIdx.x, b = blockIdx.y;
    const uint32_t* row = usim + ((long)b * NP + n) * MNP;
    int t = threadIdx.x, w = t >> 5, lane = t & 31;

    __shared__ uint32_t sv[MNP];
    __shared__ uint32_t hist[8][264];
    __shared__ uint32_t wsum[8];
    __shared__ uint32_t sh_prefix, sh_needed, sh_cnt, sh_ecnt;
    __shared__ int elist[CAND];

    #pragma unroll
    for (int j = 0; j < MNP / 1024; j++) {
        int m4 = t + j * 256;
        *reinterpret_cast<uint4*>(&sv[m4 * 4]) =
            *reinterpret_cast<const uint4*>(&row[m4 * 4]);
    }

    uint32_t prefix = 0, pmask = 0;
    int needed = CAND;

    #pragma unroll
    for (int shift = 24; shift >= 0; shift -= 8) {
        #pragma unroll
        for (int i = 0; i < 8; i++) hist[i][t] = 0;
        __syncthreads();

        #pragma unroll
        for (int j = 0; j < MNP / 256; j++) {
            uint32_t u = sv[t + j * 256];
            if ((u & pmask) == prefix)
                atomicAdd(&hist[w][(u >> shift) & 255u], 1u);
        }
        __syncthreads();

        uint32_t cnt0 = 0;
        #pragma unroll
        for (int k = 0; k < 8; k++) cnt0 += hist[k][t];

        uint32_t c = cnt0;
        #pragma unroll
        for (int off = 1; off < 32; off <<= 1) {
            uint32_t v = __shfl_down_sync(0xffffffffu, c, off);
            if (lane + off < 32) c += v;
        }
        if (lane == 0) wsum[w] = c;
        __syncthreads();
        uint32_t wsuf = 0;
        #pragma unroll
        for (int k = 0; k < 8; k++) if (k > w) wsuf += wsum[k];
        uint32_t suf = c + wsuf;
        uint32_t above = suf - cnt0;

        if ((int)above < needed && (int)suf >= needed) {
            sh_prefix = prefix | ((uint32_t)t << shift);
            sh_needed = (uint32_t)(needed - (int)above);
        }
        __syncthreads();
        prefix = sh_prefix;
        needed = (int)sh_needed;
        pmask |= (0xFFu << shift);
        __syncthreads();
    }

    if (t == 0) { sh_cnt = 0; sh_ecnt = 0; }
    __syncthreads();

    const uint32_t T = prefix;
    const int rem = needed;
    int* out = cand + ((long)b * NP + n) * CAND;

    #pragma unroll
    for (int j = 0; j < MNP / 256; j++) {
        int m = t + j * 256;
        uint32_t u = sv[m];
        if (u > T) {
            int pos = (int)atomicAdd(&sh_cnt, 1u);
            out[pos] = m;
        } else if (u == T) {
            int ep = (int)atomicAdd(&sh_ecnt, 1u);
            if (ep < CAND) elist[ep] = m;
        }
    }
    __syncthreads();

    if (t == 0) {
        int base = (int)sh_cnt;
        int ec = (int)sh_ecnt; if (ec > CAND) ec = CAND;
        int last = -1;
        for (int i = 0; i < rem; i++) {
            int best = 0x7fffffff;
            for (int j = 0; j < ec; j++) {
                int v = elist[j];
                if (v > last && v < best) best = v;
            }
            out[base + i] = best;
            last = best;
        }
    }
}

// ---------------------------------------------------------------------------
// Exact fp32 rescoring of CAND candidates per (n,b); select exact top-32.
// ---------------------------------------------------------------------------
__global__ void __launch_bounds__(256) rescore_kernel(
    const float* __restrict__ tgt, const float* __restrict__ memory,
    const float* __restrict__ mnorm, const int* __restrict__ cand,
    int* __restrict__ rns)
{
    int n = blockIdx.x, b = blockIdx.y;
    int t = threadIdx.x, w = t >> 5, lane = t & 31;
    __shared__ int   cidx[CAND];
    __shared__ float csc[CAND];
    __shared__ uint32_t cnt;

    if (t < CAND) cidx[t] = cand[((long)b * NP + n) * CAND + t];
    if (t == 0) cnt = 0;
    __syncthreads();

    const float* trow = tgt + ((long)n * BSZ + b) * DIM;
    #pragma unroll
    for (int j = 0; j < CAND / 8; j++) {
        int ci = w * (CAND / 8) + j;
        int m = cidx[ci];
        const float* mrow = memory + ((long)m * BSZ + b) * DIM;
        float s = 0.f;
        #pragma unroll
        for (int i = 0; i < 2; i++) {
            int d = lane * 4 + i * 128;
            float4 a = *reinterpret_cast<const float4*>(trow + d);
            float4 v = *reinterpret_cast<const float4*>(mrow + d);
            s = fmaf(a.x, v.x, s); s = fmaf(a.y, v.y, s);
            s = fmaf(a.z, v.z, s); s = fmaf(a.w, v.w, s);
        }
        #pragma unroll
        for (int o = 16; o; o >>= 1) s += __shfl_xor_sync(0xffffffffu, s, o);
        if (lane == 0) csc[ci] = s * mnorm[(long)m * BSZ + b];
    }
    __syncthreads();

    if (t < CAND) {
        float sc = csc[t]; int mi = cidx[t];
        int rank = 0;
        #pragma unroll
        for (int k = 0; k < CAND; k++) {
            float so = csc[k]; int mo = cidx[k];
            if (so > sc || (so == sc && mo < mi)) rank++;
        }
        if (rank < TOPK) {
            int pos = (int)atomicAdd(&cnt, 1u);
            rns[((long)b * NP + n) * TOPK + pos] = mi;
        }
    }
}

// ---------------------------------------------------------------------------
// Fused sparse cross-attention + LN1 + qadd=t1+qpos
// ---------------------------------------------------------------------------
__global__ void cross_ln_kernel(const float* __restrict__ Q,
                                const float* __restrict__ Kb,
                                const float* __restrict__ Vb,
                                const int*   __restrict__ rns,
                                const float* __restrict__ tgt,
                                const float* __restrict__ w,
                                const float* __restrict__ beta,
                                const float* __restrict__ qpos,
                                float* __restrict__ t1,
                                float* __restrict__ qadd)
{
    int n = blockIdx.x, b = blockIdx.y;
    int t = threadIdx.x, h = t >> 5, lane = t & 31;
    __shared__ int idx[TOPK];
    __shared__ float red[8];
    if (t < TOPK) idx[t] = rns[((long)b * NP + n) * TOPK + t];
    __syncthreads();

    long rowoff = ((long)n * BSZ + b) * DIM;
    float q = Q[rowoff + h * HD + lane];

    float myscore = -INFINITY;
    #pragma unroll
    for (int j = 0; j < TOPK; j++) {
        float prod = q * Kb[((long)idx[j] * BSZ + b) * DIM + h * HD + lane];
        #pragma unroll
        for (int o = 16; o; o >>= 1) prod += __shfl_xor_sync(0xffffffffu, prod, o);
        if (lane == j) myscore = prod * ATT_SCALE;
    }
    float mx = myscore;
    #pragma unroll
    for (int o = 16; o; o >>= 1) mx = fmaxf(mx, __shfl_xor_sync(0xffffffffu, mx, o));
    float e = expf(myscore - mx);
    float s = e;
    #pragma unroll
    for (int o = 16; o; o >>= 1) s += __shfl_xor_sync(0xffffffffu, s, o);
    float p = e / s;

    float acc = 0.f;
    #pragma unroll
    for (int j = 0; j < TOPK; j++) {
        float pj = __shfl_sync(0xffffffffu, p, j);
        acc = fmaf(pj, Vb[((long)idx[j] * BSZ + b) * DIM + h * HD + lane], acc);
    }

    float x = tgt[rowoff + t] + acc;
    float sum = x;
    #pragma unroll
    for (int o = 16; o; o >>= 1) sum += __shfl_xor_sync(0xffffffffu, sum, o);
    if (lane == 0) red[h] = sum;
    __syncthreads();
    float tot = 0.f;
    #pragma unroll
    for (int k = 0; k < 8; k++) tot += red[k];
    float mu = tot * (1.0f / DIM);
    __syncthreads();

    float d = x - mu;
    float s2 = d * d;
    #pragma unroll
    for (int o = 16; o; o >>= 1) s2 += __shfl_xor_sync(0xffffffffu, s2, o);
    if (lane == 0) red[h] = s2;
    __syncthreads();
    float tot2 = 0.f;
    #pragma unroll
    for (int k = 0; k < 8; k++) tot2 += red[k];
    float var = tot2 * (1.0f / DIM);

    float t1v = d * rsqrtf(var + LN_EPS) * w[t] + beta[t];
    t1[rowoff + t]   = t1v;
    qadd[rowoff + t] = t1v + qpos[rowoff + t];
}

// ---------------------------------------------------------------------------
// Fused flash self-attention
// ---------------------------------------------------------------------------
__global__ void __launch_bounds__(256) flash_sa_kernel(
    const float* __restrict__ QK2, const float* __restrict__ V2,
    float* __restrict__ sa)
{
    constexpr int QP = 36, KP = 36, VP = 36, PP = 36, CH = 32, NCH = NP / CH;
    __shared__ float Qs[128 * QP];
    __shared__ float Ks[CH * KP];
    __shared__ float Vs[HD * VP];
    __shared__ float Ps[128 * PP];

    const int q0 = blockIdx.x * 128;
    const int bh = blockIdx.y;
    const int b  = bh >> 3, h = bh & 7;
    const int t  = threadIdx.x, lane = t & 31, wm = t >> 5;

    {
        int r = t >> 1, c0 = (t & 1) * 16;
        const float* src = QK2 + ((long)(q0 + r) * BSZ + b) * 512 + h * HD + c0;
        #pragma unroll
        for (int i = 0; i < 4; i++)
            *reinterpret_cast<float4*>(&Qs[r * QP + c0 + i * 4]) =
                *reinterpret_cast<const float4*>(src + i * 4);
    }

    float m0 = -INFINITY, m1 = -INFINITY, l0 = 0.f, l1 = 0.f;
    float o[4][4] = {};
    const int rA  = wm * 16 + (lane >> 2);
    const int cq  = lane & 3;

    for (int kt = 0; kt < NCH; kt++) {
        if (t < 64) {
            int r = t >> 1, c0 = (t & 1) * 16;
            const float* src = QK2 + ((long)(kt * CH + r) * BSZ + b) * 512 + DIM + h * HD + c0;
            #pragma unroll
            for (int i = 0; i < 4; i++)
                *reinterpret_cast<float4*>(&Ks[r * KP + c0 + i * 4]) =
                    *reinterpret_cast<const float4*>(src + i * 4);
        } else if (t < 128) {
            int tt = t - 64;
            int key = tt >> 1, c0 = (tt & 1) * 16;
            const float* src = V2 + ((long)(kt * CH + key) * BSZ + b) * DIM + h * HD + c0;
            #pragma unroll
            for (int i = 0; i < 4; i++) {
                float4 v = *reinterpret_cast<const float4*>(src + i * 4);
                Vs[(c0 + i * 4 + 0) * VP + key] = ftf32(v.x);
                Vs[(c0 + i * 4 + 1) * VP + key] = ftf32(v.y);
                Vs[(c0 + i * 4 + 2) * VP + key] = ftf32(v.z);
                Vs[(c0 + i * 4 + 3) * VP + key] = ftf32(v.w);
            }
        }
        __syncthreads();

        float s[4][4];
        #pragma unroll
        for (int nt = 0; nt < 4; nt++)
            #pragma unroll
            for (int e = 0; e < 4; e++) s[nt][e] = 0.f;

        const uint32_t* qsp = reinterpret_cast<const uint32_t*>(Qs);
        const uint32_t* ksp = reinterpret_cast<const uint32_t*>(Ks);
        #pragma unroll
        for (int ks = 0; ks < 4; ks++) {
            int cb = ks * 8 + cq;
            uint32_t a0 = qsp[rA * QP + cb];
            uint32_t a1 = qsp[(rA + 8) * QP + cb];
            uint32_t a2 = qsp[rA * QP + cb + 4];
            uint32_t a3 = qsp[(rA + 8) * QP + cb + 4];
            #pragma unroll
            for (int nt = 0; nt < 4; nt++) {
                int nb = nt * 8 + (lane >> 2);
                uint32_t b0 = ksp[nb * KP + cb];
                uint32_t b1 = ksp[nb * KP + cb + 4];
                float* c = s[nt];
                asm volatile(
                    "mma.sync.aligned.m16n8k8.row.col.f32.tf32.tf32.f32 "
                    "{%0,%1,%2,%3}, {%4,%5,%6,%7}, {%8,%9}, {%0,%1,%2,%3};"
                    : "+f"(c[0]), "+f"(c[1]), "+f"(c[2]), "+f"(c[3])
                    : "r"(a0), "r"(a1), "r"(a2), "r"(a3), "r"(b0), "r"(b1));
            }
        }

        float mxA = -INFINITY, mxB = -INFINITY;
        #pragma unroll
        for (int nt = 0; nt < 4; nt++) {
            #pragma unroll
            for (int e = 0; e < 4; e++) s[nt][e] *= ATT_SCALE;
            mxA = fmaxf(mxA, fmaxf(s[nt][0], s[nt][1]));
            mxB = fmaxf(mxB, fmaxf(s[nt][2], s[nt][3]));
        }
        #pragma unroll
        for (int off = 1; off <= 2; off <<= 1) {
            mxA = fmaxf(mxA, __shfl_xor_sync(0xffffffffu, mxA, off));
            mxB = fmaxf(mxB, __shfl_xor_sync(0xffffffffu, mxB, off));
        }
        float mA = fmaxf(m0, mxA), mB = fmaxf(m1, mxB);
        float sc0 = expf(m0 - mA), sc1 = expf(m1 - mB);

        float sumA = 0.f, sumB = 0.f;
        float pr[4][4];
        #pragma unroll
        for (int nt = 0; nt < 4; nt++) {
            pr[nt][0] = expf(s[nt][0] - mA);
            pr[nt][1] = expf(s[nt][1] - mA);
            pr[nt][2] = expf(s[nt][2] - mB);
            pr[nt][3] = expf(s[nt][3] - mB);
            sumA += pr[nt][0] + pr[nt][1];
            sumB += pr[nt][2] + pr[nt][3];
        }
        #pragma unroll
        for (int off = 1; off <= 2; off <<= 1) {
            sumA += __shfl_xor_sync(0xffffffffu, sumA, off);
            sumB += __shfl_xor_sync(0xffffffffu, sumB, off);
        }
        l0 = l0 * sc0 + sumA;
        l1 = l1 * sc1 + sumB;
        m0 = mA; m1 = mB;

        #pragma unroll
        for (int nt = 0; nt < 4; nt++) {
            float2 pa = make_float2(ftf32(pr[nt][0]), ftf32(pr[nt][1]));
            float2 pb = make_float2(ftf32(pr[nt][2]), ftf32(pr[nt][3]));
            *reinterpret_cast<float2*>(&Ps[rA * PP + nt * 8 + cq * 2]) = pa;
            *reinterpret_cast<float2*>(&Ps[(rA + 8) * PP + nt * 8 + cq * 2]) = pb;
        }
        __syncwarp();

        #pragma unroll
        for (int nt = 0; nt < 4; nt++) {
            o[nt][0] *= sc0; o[nt][1] *= sc0;
            o[nt][2] *= sc1; o[nt][3] *= sc1;
        }
        const uint32_t* psp = reinterpret_cast<const uint32_t*>(Ps);
        const uint32_t* vsp = reinterpret_cast<const uint32_t*>(Vs);
        #pragma unroll
        for (int ks = 0; ks < 4; ks++) {
            int cb = ks * 8 + cq;
            uint32_t a0 = psp[rA * PP + cb];
            uint32_t a1 = psp[(rA + 8) * PP + cb];
            uint32_t a2 = psp[rA * PP + cb + 4];
            uint32_t a3 = psp[(rA + 8) * PP + cb + 4];
            #pragma unroll
            for (int nt = 0; nt < 4; nt++) {
                int nb = nt * 8 + (lane >> 2);
                uint32_t b0 = vsp[nb * VP + cb];
                uint32_t b1 = vsp[nb * VP + cb + 4];
                float* c = o[nt];
                asm volatile(
                    "mma.sync.aligned.m16n8k8.row.col.f32.tf32.tf32.f32 "
                    "{%0,%1,%2,%3}, {%4,%5,%6,%7}, {%8,%9}, {%0,%1,%2,%3};"
                    : "+f"(c[0]), "+f"(c[1]), "+f"(c[2]), "+f"(c[3])
                    : "r"(a0), "r"(a1), "r"(a2), "r"(a3), "r"(b0), "r"(b1));
            }
        }
        __syncthreads();
    }

    float i0 = 1.f / l0, i1 = 1.f / l1;
    #pragma unroll
    for (int nt = 0; nt < 4; nt++) {
        int col = h * HD + nt * 8 + cq * 2;
        long rowA = (long)(q0 + rA) * BSZ + b;
        long rowB = (long)(q0 + rA + 8) * BSZ + b;
        *reinterpret_cast<float2*>(&sa[rowA * DIM + col]) =
            make_float2(o[nt][0] * i0, o[nt][1] * i0);
        *reinterpret_cast<float2*>(&sa[rowB * DIM + col]) =
            make_float2(o[nt][2] * i1, o[nt][3] * i1);
    }
}

// ---------------------------------------------------------------------------
// out = LayerNorm(a + c) * w + beta
// ---------------------------------------------------------------------------
__global__ void add_ln_kernel(const float* __restrict__ a, const float* __restrict__ c,
                              const float* __restrict__ w, const float* __restrict__ beta,
                              float* __restrict__ out)
{
    long r = blockIdx.x;
    int  t = threadIdx.x;
    float x = a[r * DIM + t] + c[r * DIM + t];
    __shared__ float red[8];

    float s = x;
    #pragma unroll
    for (int o = 16; o; o >>= 1) s += __shfl_xor_sync(0xffffffffu, s, o);
    if ((t & 31) == 0) red[t >> 5] = s;
    __syncthreads();
    float tot = 0.f;
    #pragma unroll
    for (int k = 0; k < 8; k++) tot += red[k];
    float mu = tot * (1.0f / DIM);
    __syncthreads();

    float d  = x - mu;
    float s2 = d * d;
    #pragma unroll
    for (int o = 16; o; o >>= 1) s2 += __shfl_xor_sync(0xffffffffu, s2, o);
    if ((t & 31) == 0) red[t >> 5] = s2;
    __syncthreads();
    float tot2 = 0.f;
    #pragma unroll
    for (int k = 0; k < 8; k++) tot2 += red[k];
    float var = tot2 * (1.0f / DIM);

    out[r * DIM + t] = d * rsqrtf(var + LN_EPS) * w[t] + beta[t];
}

// ---------------------------------------------------------------------------
// out = LN(t2 + p0 + p1 + p2 + p3 + bias)
// ---------------------------------------------------------------------------
__global__ void ln3_fused_kernel(const float* __restrict__ t2,
                                 const float* __restrict__ pp,
                                 long pstride,
                                 const float* __restrict__ bias,
                                 const float* __restrict__ w,
                                 const float* __restrict__ beta,
                                 float* __restrict__ out)
{
    long r = blockIdx.x;
    int  t = threadIdx.x;
    long o4 = r * DIM + t;
    float x = t2[o4] + ((pp[o4] + pp[o4 + pstride]) +
                        (pp[o4 + 2 * pstride] + pp[o4 + 3 * pstride]) + bias[t]);
    __shared__ float red[8];

    float s = x;
    #pragma unroll
    for (int o = 16; o; o >>= 1) s += __shfl_xor_sync(0xffffffffu, s, o);
    if ((t & 31) == 0) red[t >> 5] = s;
    __syncthreads();
    float tot = 0.f;
    #pragma unroll
    for (int k = 0; k < 8; k++) tot += red[k];
    float mu = tot * (1.0f / DIM);
    __syncthreads();

    float d  = x - mu;
    float s2 = d * d;
    #pragma unroll
    for (int o = 16; o; o >>= 1) s2 += __shfl_xor_sync(0xffffffffu, s2, o);
    if ((t & 31) == 0) red[t >> 5] = s2;
    __syncthreads();
    float tot2 = 0.f;
    #pragma unroll
    for (int k = 0; k < 8; k++) tot2 += red[k];
    float var = tot2 * (1.0f / DIM);

    out[r * DIM + t] = d * rsqrtf(var + LN_EPS) * w[t] + beta[t];
}

// ---------------------------------------------------------------------------
// Launch
// ---------------------------------------------------------------------------
extern "C" void kernel_launch(void* const* d_in, const int* in_sizes, int n_in,
                              void* d_out, int out_size)
{
    const float* tgt      = (const float*)d_in[0];
    const float* memory   = (const float*)d_in[1];
    const float* qpos     = (const float*)d_in[2];
    const float* kpos     = (const float*)d_in[3];
    const float* cw1      = (const float*)d_in[4];
    const float* cb1      = (const float*)d_in[5];
    const float* cw2      = (const float*)d_in[6];
    const float* cb2      = (const float*)d_in[7];
    const float* cw3      = (const float*)d_in[8];
    const float* cb3      = (const float*)d_in[9];
    const float* sa_in_w  = (const float*)d_in[10];
    const float* sa_in_b  = (const float*)d_in[11];
    const float* sa_out_w = (const float*)d_in[12];
    const float* sa_out_b = (const float*)d_in[13];
    const float* ln1_w    = (const float*)d_in[14];
    const float* ln1_b    = (const float*)d_in[15];
    const float* ln2_w    = (const float*)d_in[16];
    const float* ln2_b    = (const float*)d_in[17];
    const float* ln3_w    = (const float*)d_in[18];
    const float* ln3_b    = (const float*)d_in[19];
    const float* ff1_w    = (const float*)d_in[20];
    const float* ff1_b    = (const float*)d_in[21];
    const float* ff2_w    = (const float*)d_in[22];
    const float* ff2_b    = (const float*)d_in[23];
    float* out = (float*)d_out;

    void *p;
    cudaGetSymbolAddress(&p, g_usim);  uint32_t* usim = (uint32_t*)p;
    cudaGetSymbolAddress(&p, g_mnorm); float* mnorm = (float*)p;
    cudaGetSymbolAddress(&p, g_cand);  int*   cand  = (int*)p;
    cudaGetSymbolAddress(&p, g_rns);   int*   rns   = (int*)p;
    cudaGetSymbolAddress(&p, g_K);     float* Kb    = (float*)p;
    cudaGetSymbolAddress(&p, g_V);     float* Vb    = (float*)p;
    cudaGetSymbolAddress(&p, g_Q);     float* Qb    = (float*)p;
    cudaGetSymbolAddress(&p, g_t1);    float* t1    = (float*)p;
    cudaGetSymbolAddress(&p, g_QK2);   float* QK2   = (float*)p;
    cudaGetSymbolAddress(&p, g_V2);    float* V2    = (float*)p;
    cudaGetSymbolAddress(&p, g_sa);    float* sa    = (float*)p;
    cudaGetSymbolAddress(&p, g_sa2);   float* sa2   = (float*)p;
    cudaGetSymbolAddress(&p, g_t2);    float* t2    = (float*)p;
    cudaGetSymbolAddress(&p, g_ffh);   float* ffh   = (float*)p;
    cudaGetSymbolAddress(&p, g_ffo);   float* ffo   = (float*)p;
    cudaGetSymbolAddress(&p, g_madd);  float* madd  = (float*)p;
    cudaGetSymbolAddress(&p, g_qadd);  float* qadd  = (float*)p;

    const int BD = BSZ * DIM;   // 2048
    const int NB = NP * BSZ;    // 4096
    const int MB = MNP * BSZ;   // 32768

    // 1) fused pre: madd, mnorm, qadd
    pre_kernel<<<MB / 8 + NB * DIM / 4096, 256>>>(memory, kpos, madd, mnorm, tgt, qpos, qadd);

    // 2) sim (BN=128 @ 256 threads, ordermap epilogue with mnorm)
    tgemm_nt<128, 2><<<dim3(MNP / 128, NP / 128, BSZ), 256>>>(
        tgt, memory, mnorm, (float*)usim,
        NP, MNP, DIM, BD, BD, MNP,
        0, DIM, 0, DIM, 0, (long)NP * MNP, 1, BSZ, 1.0f);

    // 3) radix top-48 candidates
    topk_radix<<<dim3(NP, BSZ), 256>>>(usim, cand);

    // 4) exact fp32 rescore -> exact top-32
    rescore_kernel<<<dim3(NP, BSZ), 256>>>(tgt, memory, mnorm, cand, rns);

    // 5) K + V projections, BN=128 @ 256 threads, ONE launch
    tgemm_nt<128, 0><<<dim3(DIM / 128, MB / 128, 2), 256>>>(
        madd, cw2, cb2, Kb,
        MB, DIM, DIM, DIM, DIM, DIM,
        0, (long)(memory - madd),
        0, (long)(cw3 - cw2),
        0, (long)(Vb - Kb),
        (long)(cb3 - cb2), 2, 1.0f);
    // Q projection (small grid, BN=64)
    tgemm_nt<64, 0><<<dim3(DIM / 64, NB / 128, 1), 256>>>(
        qadd, cw1, cb1, Qb, NB, DIM, DIM, DIM, DIM, DIM, 0, 0, 0, 0, 0, 0, 0, 1, 1.0f);

    // 6) cross-attention + LN1 + (qadd = t1 + qpos)
    cross_ln_kernel<<<dim3(NP, BSZ), 256>>>(Qb, Kb, Vb, rns, tgt, ln1_w, ln1_b, qpos, t1, qadd);

    // 7) self-attn projections
    tgemm_nt<64, 0><<<dim3(2 * DIM / 64, NB / 128, 1), 256>>>(
        qadd, sa_in_w, sa_in_b, QK2, NB, 2 * DIM, DIM, DIM, DIM, 2 * DIM, 0, 0, 0, 0, 0, 0, 0, 1, 1.0f);
    tgemm_nt<64, 0><<<dim3(DIM / 64, NB / 128, 1), 256>>>(
        t1, sa_in_w + 2 * DIM * DIM, sa_in_b + 2 * DIM, V2,
        NB, DIM, DIM, DIM, DIM, DIM, 0, 0, 0, 0, 0, 0, 0, 1, 1.0f);

    // 8) flash self-attention
    flash_sa_kernel<<<dim3(NP / 128, BSZ * NH), 256>>>(QK2, V2, sa);

    // 9) out projection, t2 = LN(t1 + sa2)
    tgemm_nt<64, 0><<<dim3(DIM / 64, NB / 128, 1), 256>>>(
        sa, sa_out_w, sa_out_b, sa2, NB, DIM, DIM, DIM, DIM, DIM, 0, 0, 0, 0, 0, 0, 0, 1, 1.0f);
    add_ln_kernel<<<NB, 256>>>(t1, sa2, ln2_w, ln2_b, t2);

    // 10) FFN1 (GELU, BN=128 @ 256 threads)
    tgemm_nt<128, 1><<<dim3(FF / 128, NB / 128, 1), 256>>>(
        t2, ff1_w, ff1_b, ffh, NB, FF, DIM, DIM, DIM, FF, 0, 0, 0, 0, 0, 0, 0, 1, 1.0f);
    // 11) FFN2 split-K=4
    tgemm_nt<64, 0><<<dim3(DIM / 64, NB / 128, 4), 256>>>(
        ffh, ff2_w, nullptr, ffo, NB, DIM, FF / 4, FF, FF, DIM,
        0, FF / 4, 0, FF / 4, 0, (long)NB * DIM, 0, 4, 1.0f);
    // 12) final fused reduce(4) + LN
    ln3_fused_kernel<<<NB, 256>>>(t2, ffo, (long)NB * DIM, ff2_b, ln3_w, ln3_b, out);
}